// round 15
// baseline (speedup 1.0000x reference)
#include <cuda_runtime.h>
#include <cstdint>

// ---------------------------------------------------------------------------
// MultiHeadedEMA == causal + anti-causal first-order EMA per (head, channel).
//   fwd: u[t] = q*u[t-1] + x[t] ;  rev: u[t] = q*u[t+1] + x[t]
//   out[b,l,d] = sum_h wf[h,d]*uf + wr[h,d]*ur,  w = expansion*reduction*a
// Round-15: seeded scan split by linearity:
//   u_full[i] = u_local[i] + q^{i+1} * P   (P = incoming prefix state)
// Kernel B computes the full weighted LOCAL output (x loads + 512 fma2,
// independent of kernel A) BEFORE griddepcontrol.wait; post-wait only the
// windowed lookback (P) + geometric correction + store remain. PDL overlaps
// kernel A entirely under B's prologue.
// ---------------------------------------------------------------------------

constexpr int kB = 2;
constexpr int kL = 2048;
constexpr int kD = 1024;
constexpr int kH = 8;

constexpr int kChunk   = 16;
constexpr int kNChunk  = kL / kChunk;             // 128
constexpr int kCols    = 256;                     // d-columns per block
constexpr int kThreads = 128;                     // 2 cols/thread -> f32x2
constexpr int kDTiles  = kD / kCols;              // 4
constexpr int kBlocks  = kB * kNChunk * kDTiles;  // 1024

// Per-chunk end states (fwd / rev), L2-resident scratch (16 MB).
__device__ __align__(16) float g_sf[kB][kNChunk][kH][kD];
__device__ __align__(16) float g_sr[kB][kNChunk][kH][kD];

using u64 = unsigned long long;

__device__ __forceinline__ u64 pack2(float lo, float hi) {
    u64 r;
    asm("mov.b64 %0, {%1, %2};"
        : "=l"(r) : "r"(__float_as_uint(lo)), "r"(__float_as_uint(hi)));
    return r;
}
__device__ __forceinline__ u64 fma2(u64 a, u64 b, u64 c) {
    u64 r;
    asm("fma.rn.f32x2 %0, %1, %2, %3;" : "=l"(r) : "l"(a), "l"(b), "l"(c));
    return r;
}
__device__ __forceinline__ u64 mul2(u64 a, u64 b) {
    u64 r;
    asm("mul.rn.f32x2 %0, %1, %2;" : "=l"(r) : "l"(a), "l"(b));
    return r;
}
__device__ __forceinline__ u64 add2(u64 a, u64 b) {
    u64 r;
    asm("add.rn.f32x2 %0, %1, %2;" : "=l"(r) : "l"(a), "l"(b));
    return r;
}
__device__ __forceinline__ void store_cs(u64* p, u64 v) {
    float2 f;
    f.x = __uint_as_float((unsigned)(v & 0xffffffffull));
    f.y = __uint_as_float((unsigned)(v >> 32));
    __stcs(reinterpret_cast<float2*>(p), f);
}

// fp32 sigmoid; use sigp(-v) for the (1 - sigmoid(v)) term (no cancellation).
__device__ __forceinline__ float sigp(float v) { return 1.0f / (1.0f + expf(-v)); }

// ---------------------------------------------------------------------------
// Kernel A: per-chunk local scans (zero-init), publish fwd/rev end states.
// DRAM-roofline; fires the PDL trigger at entry so B co-runs.
// ---------------------------------------------------------------------------
__global__ void __launch_bounds__(kThreads)
ema_agg(const float* __restrict__ x,
        const float* __restrict__ al,  const float* __restrict__ da,
        const float* __restrict__ ral, const float* __restrict__ rda)
{
    asm volatile("griddepcontrol.launch_dependents;");

    __shared__ float s_q[2][kH];

    const int tid = threadIdx.x;
    if (tid < 2 * kH) {
        const int dir = tid >= kH;
        const int h   = tid & (kH - 1);
        const float av = dir ? ral[h] : al[h];
        const float dv = dir ? rda[h] : da[h];
        s_q[dir][h] = sigp(-av) * sigp(dv);
    }

    const int blk = blockIdx.x;
    const int dt = blk & (kDTiles - 1);
    const int c  = (blk >> 2) & (kNChunk - 1);
    const int b  = blk >> 9;

    const u64* xs = reinterpret_cast<const u64*>(
        x + ((size_t)b * kL + (size_t)c * kChunk) * kD + dt * kCols) + tid;
    const int d = dt * kCols + 2 * tid;

    u64 xv[kChunk];
#pragma unroll
    for (int i = 0; i < kChunk; ++i) xv[i] = xs[i * (kD / 2)];

    __syncthreads();

    u64 q2[kH], s[kH];
#pragma unroll
    for (int h = 0; h < kH; ++h) {
        float q = s_q[0][h];
        q2[h] = pack2(q, q);
        s[h] = 0ull;
    }
#pragma unroll
    for (int i = 0; i < kChunk; ++i)
#pragma unroll
        for (int h = 0; h < kH; ++h) s[h] = fma2(q2[h], s[h], xv[i]);
#pragma unroll
    for (int h = 0; h < kH; ++h)
        *reinterpret_cast<u64*>(&g_sf[b][c][h][d]) = s[h];

#pragma unroll
    for (int h = 0; h < kH; ++h) {
        float q = s_q[1][h];
        q2[h] = pack2(q, q);
        s[h] = 0ull;
    }
#pragma unroll
    for (int i = kChunk - 1; i >= 0; --i)
#pragma unroll
        for (int h = 0; h < kH; ++h) s[h] = fma2(q2[h], s[h], xv[i]);
#pragma unroll
    for (int h = 0; h < kH; ++h)
        *reinterpret_cast<u64*>(&g_sr[b][c][h][d]) = s[h];
}

// ---------------------------------------------------------------------------
// Kernel B (PDL secondary):
//   PRE-WAIT  : weighted local fwd+rev scans into smem acc (independent of A)
//   POST-WAIT : windowed lookback -> Pf/Pr, geometric correction, store out.
// ---------------------------------------------------------------------------
__global__ void __launch_bounds__(kThreads)
ema_out(const float* __restrict__ x,
        const float* __restrict__ ex,  const float* __restrict__ re,
        const float* __restrict__ al,  const float* __restrict__ da,
        const float* __restrict__ ral, const float* __restrict__ rda,
        float* __restrict__ out)
{
    __shared__ u64 acc[kChunk * kThreads];           // 16 KB local partials
    __shared__ float s_q[2][kH], s_a[2][kH], s_qc[2][kH];
    __shared__ int s_W[2];

    const int tid = threadIdx.x;
    const int blk = blockIdx.x;
    const int dt = blk & (kDTiles - 1);
    const int c  = (blk >> 2) & (kNChunk - 1);
    const int b  = blk >> 9;

    const u64* xs = reinterpret_cast<const u64*>(
        x + ((size_t)b * kL + (size_t)c * kChunk) * kD + dt * kCols) + tid;
    const int d = dt * kCols + 2 * tid;

    // ---- constants (independent of A) --------------------------------------
    if (tid < 2 * kH) {
        const int dr = tid >= kH;
        const int h  = tid & (kH - 1);
        const float av = dr ? ral[h] : al[h];
        const float dv = dr ? rda[h] : da[h];
        s_a[dr][h] = sigp(av);
        float q = sigp(-av) * sigp(dv);
        s_q[dr][h] = q;
        float qc = q;
#pragma unroll
        for (int k = 0; k < 4; ++k) qc *= qc;        // q^16
        s_qc[dr][h] = qc;
    }
    __syncthreads();
    if (tid < 2) {
        float m = 0.0f;
#pragma unroll
        for (int h = 0; h < kH; ++h) m = fmaxf(m, s_qc[tid][h]);
        // W = ceil(ln(1e-8)/ln(qcmax)), clamped to full history.
        int W = kNChunk;
        if (m <= 0.0f) W = 0;
        else {
            float lq = logf(m);
            if (lq < -1e-20f) {
                float w = ceilf(-18.4207f / lq);
                W = (w >= (float)kNChunk) ? kNChunk : (int)w;
            }
        }
        s_W[tid] = W;
    }
    __syncthreads();

    // ---- weights for both directions (independent of A) --------------------
    u64 wF[kH], wR[kH], qF[kH], qR[kH];
#pragma unroll
    for (int h = 0; h < kH; ++h) {
        qF[h] = pack2(s_q[0][h], s_q[0][h]);
        qR[h] = pack2(s_q[1][h], s_q[1][h]);
        float a = s_a[0][h];
        float e0 = ex[h * kD + d], e1 = ex[h * kD + d + 1];
        float r0 = re[h * kD + d], r1 = re[h * kD + d + 1];
        wF[h] = pack2(e0 * r0 * a, e1 * r1 * a);
        a = s_a[1][h];
        e0 = ex[(kH + h) * kD + d]; e1 = ex[(kH + h) * kD + d + 1];
        r0 = re[(kH + h) * kD + d]; r1 = re[(kH + h) * kD + d + 1];
        wR[h] = pack2(e0 * r0 * a, e1 * r1 * a);
    }

    // ---- PRE-WAIT: weighted local fwd scan (zero-init) ---------------------
    {
        u64 u[kH];
#pragma unroll
        for (int h = 0; h < kH; ++h) u[h] = 0ull;
#pragma unroll
        for (int i = 0; i < kChunk; ++i) {
            u64 xv = xs[i * (kD / 2)];
            u64 fs = 0ull;
#pragma unroll
            for (int h = 0; h < kH; ++h) {
                u[h] = fma2(qF[h], u[h], xv);
                fs   = fma2(wF[h], u[h], fs);
            }
            acc[i * kThreads + tid] = fs;
        }
    }
    // ---- PRE-WAIT: weighted local rev scan, accumulate into acc ------------
    {
        u64 u[kH];
#pragma unroll
        for (int h = 0; h < kH; ++h) u[h] = 0ull;
#pragma unroll
        for (int i = kChunk - 1; i >= 0; --i) {
            u64 xv = xs[i * (kD / 2)];               // L1 hit
            u64 rs = 0ull;
#pragma unroll
            for (int h = 0; h < kH; ++h) {
                u[h] = fma2(qR[h], u[h], xv);
                rs   = fma2(wR[h], u[h], rs);
            }
            acc[i * kThreads + tid] = add2(acc[i * kThreads + tid], rs);
        }
    }

    // ---- wait for kernel A's aggregates (A fully overlapped above) ---------
    asm volatile("griddepcontrol.wait;");

    const int dh = d >> 1;
    const u64* bsf = reinterpret_cast<const u64*>(g_sf) +
                     (size_t)b * kNChunk * kH * (kD / 2) + dh;
    const u64* bsr = reinterpret_cast<const u64*>(g_sr) +
                     (size_t)b * kNChunk * kH * (kD / 2) + dh;

    u64* od = reinterpret_cast<u64*>(
        out + ((size_t)b * kL + (size_t)c * kChunk) * kD + dt * kCols) + tid;

    // ---- POST-WAIT: lookback prefixes Pf / Pr -------------------------------
    u64 Pf[kH], Pr[kH];
    {
        const int Wf = min(s_W[0], c);
        float wk[kH];
#pragma unroll
        for (int h = 0; h < kH; ++h) { Pf[h] = 0ull; wk[h] = 1.0f; }
        for (int k = 0; k < Wf; ++k) {
            const u64* row = bsf + (size_t)(c - 1 - k) * kH * (kD / 2);
#pragma unroll
            for (int h = 0; h < kH; ++h) {
                Pf[h] = fma2(pack2(wk[h], wk[h]), row[h * (kD / 2)], Pf[h]);
                wk[h] *= s_qc[0][h];
            }
        }
        const int Wr = min(s_W[1], kNChunk - 1 - c);
#pragma unroll
        for (int h = 0; h < kH; ++h) { Pr[h] = 0ull; wk[h] = 1.0f; }
        for (int k = 0; k < Wr; ++k) {
            const u64* row = bsr + (size_t)(c + 1 + k) * kH * (kD / 2);
#pragma unroll
            for (int h = 0; h < kH; ++h) {
                Pr[h] = fma2(pack2(wk[h], wk[h]), row[h * (kD / 2)], Pr[h]);
                wk[h] *= s_qc[1][h];
            }
        }
    }

    // ---- POST-WAIT: corrections. fwd: acc[i] += sum_h wF*q^{i+1}*Pf --------
    {
        u64 t[kH];
#pragma unroll
        for (int h = 0; h < kH; ++h)
            t[h] = mul2(qF[h], mul2(wF[h], Pf[h]));   // i = 0 term
#pragma unroll
        for (int i = 0; i < kChunk; ++i) {
            u64 cf = t[0];
#pragma unroll
            for (int h = 1; h < kH; ++h) cf = add2(cf, t[h]);
            acc[i * kThreads + tid] = add2(acc[i * kThreads + tid], cf);
#pragma unroll
            for (int h = 0; h < kH; ++h) t[h] = mul2(qF[h], t[h]);
        }
    }
    // ---- rev: out[i] = acc[i] + sum_h wR*q^{16-i}*Pr, store once -----------
    {
        u64 t[kH];
#pragma unroll
        for (int h = 0; h < kH; ++h)
            t[h] = mul2(qR[h], mul2(wR[h], Pr[h]));   // i = 15 term
#pragma unroll
        for (int i = kChunk - 1; i >= 0; --i) {
            u64 cr = t[0];
#pragma unroll
            for (int h = 1; h < kH; ++h) cr = add2(cr, t[h]);
            store_cs(od + i * (kD / 2),
                     add2(acc[i * kThreads + tid], cr));
#pragma unroll
            for (int h = 0; h < kH; ++h) t[h] = mul2(qR[h], t[h]);
        }
    }
}

// ---------------------------------------------------------------------------
extern "C" void kernel_launch(void* const* d_in, const int* in_sizes, int n_in,
                              void* d_out, int out_size)
{
    const float* x   = (const float*)d_in[0];
    const float* ex  = (const float*)d_in[1];
    const float* re  = (const float*)d_in[2];
    const float* al  = (const float*)d_in[3];
    const float* da  = (const float*)d_in[4];
    const float* ral = (const float*)d_in[5];
    const float* rda = (const float*)d_in[6];
    float* out = (float*)d_out;

    ema_agg<<<kBlocks, kThreads>>>(x, al, da, ral, rda);

    // PDL: B's local scans (the heavy, A-independent part) overlap kernel A;
    // griddepcontrol.wait guards only the lookback + correction.
    cudaLaunchConfig_t cfg = {};
    cfg.gridDim  = dim3(kBlocks);
    cfg.blockDim = dim3(kThreads);
    cfg.dynamicSmemBytes = 0;
    cfg.stream = 0;
    cudaLaunchAttribute attrs[1];
    attrs[0].id = cudaLaunchAttributeProgrammaticStreamSerialization;
    attrs[0].val.programmaticStreamSerializationAllowed = 1;
    cfg.attrs = attrs;
    cfg.numAttrs = 1;
    cudaLaunchKernelEx(&cfg, ema_out, x, ex, re, al, da, ral, rda, out);
}